// round 12
// baseline (speedup 1.0000x reference)
#include <cuda_runtime.h>
#include <cstdint>

#define C_IN  64
#define OC    64
#define KNPTS 9
#define PLANE 16384
#define KTOT  576

#define THREADS 256
#define PIXB   128                  // pixels per block (M) = one image row
#define NBLK   (4 * PLANE / PIXB)   // 512

// ---- scratch (__device__ globals: allocation is forbidden) ----
__device__ float g_xhwc[(size_t)4 * PLANE * C_IN];   // NHWC x
// B in mma-fragment order: [kn][n0g][ks][nt][lane] -> {b0_hi, b1_hi, b0_lo, b1_lo}
__device__ uint4 g_wfrag[KNPTS * 2 * 4 * 4 * 32];
#define WIDX(kn, n0g, ks, nt, lane) \
    ((((((kn) * 2 + (n0g)) * 4 + (ks)) * 4 + (nt)) * 32) + (lane))

// ---- dynamic smem layout (bytes): double-buffered A tiles only ----
#define SM_AH     0                 // A hi [2] : 2 x 16384
#define SM_AL     32768             // A lo [2] : 2 x 16384
#define SM_TOTAL  65536
#define CS_STRIDE 132               // epilogue C stage row stride (floats)

// word-index swizzle (swizzle bits 2-4 only; 16B groups stay contiguous)
#define AIDX(p, kp)  (((p) << 5) + ((kp) ^ (((p) & 7) << 2)))

__device__ __forceinline__ uint32_t pack_bf16x2(float lo, float hi) {
    uint32_t r;   // d.hi = cvt(hi), d.lo = cvt(lo)
    asm("cvt.rn.bf16x2.f32 %0, %1, %2;" : "=r"(r) : "f"(hi), "f"(lo));
    return r;
}
__device__ __forceinline__ float unpack_lo(uint32_t w) { return __uint_as_float(w << 16); }
__device__ __forceinline__ float unpack_hi(uint32_t w) { return __uint_as_float(w & 0xFFFF0000u); }

__device__ __forceinline__ uint32_t smem_u32(const void* p) {
    uint32_t a;
    asm("{ .reg .u64 t; cvta.to.shared.u64 t, %1; cvt.u32.u64 %0, t; }" : "=r"(a) : "l"(p));
    return a;
}
__device__ __forceinline__ void ldm4(uint32_t* d, uint32_t addr) {
    asm volatile("ldmatrix.sync.aligned.m8n8.x4.shared.b16 {%0,%1,%2,%3}, [%4];"
                 : "=r"(d[0]), "=r"(d[1]), "=r"(d[2]), "=r"(d[3]) : "r"(addr));
}

#define MMA(C, A, B0r, B1r)                                                     \
    asm volatile("mma.sync.aligned.m16n8k16.row.col.f32.bf16.bf16.f32 "         \
                 "{%0,%1,%2,%3},{%4,%5,%6,%7},{%8,%9},{%0,%1,%2,%3};"           \
                 : "+f"(C[0]), "+f"(C[1]), "+f"(C[2]), "+f"(C[3])               \
                 : "r"(A[0]), "r"(A[1]), "r"(A[2]), "r"(A[3]), "r"(B0r), "r"(B1r))

// ---------------- NCHW -> NHWC transpose (64-pixel tiles, 1024 blocks) ----------------
__global__ __launch_bounds__(256)
void nchw_to_nhwc_kernel(const float* __restrict__ x)
{
    __shared__ float t[64][65];
    const int n   = blockIdx.x >> 8;
    const int hw0 = (blockIdx.x & 255) << 6;
    const int tid = threadIdx.x;
    const float* xn = x + ((size_t)n << 20);
#pragma unroll
    for (int k = 0; k < 4; k++) {
        const int idx = tid + k * 256;
        const int c = idx >> 4, q = idx & 15;
        const float4 v = *(const float4*)(xn + ((size_t)c << 14) + hw0 + 4 * q);
        t[c][4 * q] = v.x; t[c][4 * q + 1] = v.y; t[c][4 * q + 2] = v.z; t[c][4 * q + 3] = v.w;
    }
    __syncthreads();
    float* dst = g_xhwc + (((size_t)n << 14) + hw0) * 64;
#pragma unroll
    for (int k = 0; k < 4; k++) {
        const int idx = tid + k * 256;
        const int p = idx >> 4, cq = idx & 15;
        float4 v;
        v.x = t[4 * cq][p]; v.y = t[4 * cq + 1][p]; v.z = t[4 * cq + 2][p]; v.w = t[4 * cq + 3][p];
        *(float4*)(dst + (size_t)p * 64 + 4 * cq) = v;
    }
}

// ------- weight: bf16 hi/lo split directly into mma-fragment order -------
__global__ __launch_bounds__(256)
void wsplit_kernel(const float* __restrict__ w)
{
    const int i = blockIdx.x * 256 + threadIdx.x;   // fragment uint4 id
    if (i < KNPTS * 2 * 4 * 4 * 32) {
        const int lane = i & 31;
        const int nt   = (i >> 5) & 3;
        const int ks   = (i >> 7) & 3;
        const int n0g  = (i >> 9) & 1;
        const int kn   = i >> 10;
        const int oc   = n0g * 32 + nt * 8 + (lane >> 2);
        uint4 q;
        // b0: k-pair kp0, b1: k-pair kp0+4 (k offset +8)
        const int kp0 = ks * 8 + (lane & 3);
#pragma unroll
        for (int b = 0; b < 2; b++) {
            const int kp = kp0 + 4 * b;
            const float v0 = w[oc * KTOT + (2 * kp) * KNPTS + kn];
            const float v1 = w[oc * KTOT + (2 * kp + 1) * KNPTS + kn];
            const uint32_t hi = pack_bf16x2(v0, v1);
            const uint32_t lo = pack_bf16x2(v0 - unpack_lo(hi), v1 - unpack_hi(hi));
            if (b == 0) { q.x = hi; q.z = lo; }
            else        { q.y = hi; q.w = lo; }
        }
        g_wfrag[i] = q;
    }
}

// ---- main kernel: double-buffered pipeline, A via ldmatrix, B via LDG frags ----
extern __shared__ char smem[];

__global__ __launch_bounds__(THREADS, 2)
void dcn_mma_kernel(const float* __restrict__ offset, float* __restrict__ out)
{
    const int tid  = threadIdx.x;
    const int wid  = tid >> 5;
    const int lane = tid & 31;
    const int n       = blockIdx.x >> 7;            // 128 blocks per image
    const int pixbase = (blockIdx.x & 127) << 7;    // one full image row
    const int ohc     = pixbase >> 7;               // constant oh for this block

    const float* offn = offset + (size_t)n * (KNPTS * 2) * PLANE + pixbase;
    const float* xb   = g_xhwc + (((size_t)n) << 14) * 64;
    const uint32_t sb = smem_u32(smem);

    const int tg = tid >> 4;        // sampling task group 0..15
    const int lh = tid & 15;        // channel quad owner: channels 4lh..4lh+3

    // sampling of one (kn, buf) tile: 128 pixels x 64 ch -> bf16 hi/lo into A
    auto sample_tile = [&](int kn, int buf) {
        uint32_t* A0 = (uint32_t*)(smem + SM_AH + buf * 16384);
        uint32_t* A1 = (uint32_t*)(smem + SM_AL + buf * 16384);
        const float* offy_p = offn + (2 * kn) * PLANE;
        const float* offx_p = offn + (2 * kn + 1) * PLANE;
#pragma unroll
        for (int it = 0; it < 8; it++) {
            const int p = it * 16 + tg;                 // ow == p
            const float iy = (float)ohc + offy_p[p];    // broadcast LDG
            const float ix = (float)p   + offx_p[p];
            const float y0f = floorf(iy), x0f = floorf(ix);
            const float wy1 = iy - y0f,  wx1 = ix - x0f;
            const float wy0 = 1.f - wy1, wx0 = 1.f - wx1;
            const int x0 = (int)x0f, y0 = (int)y0f;
            const int x1 = x0 + 1,  y1 = y0 + 1;
            const float mx0 = ((unsigned)x0 < 128u) ? 1.f : 0.f;
            const float mx1 = ((unsigned)x1 < 128u) ? 1.f : 0.f;
            const float my0 = ((unsigned)y0 < 128u) ? 1.f : 0.f;
            const float my1 = ((unsigned)y1 < 128u) ? 1.f : 0.f;
            const int cx0 = min(max(x0, 0), 127), cx1 = min(max(x1, 0), 127);
            const int cy0 = min(max(y0, 0), 127), cy1 = min(max(y1, 0), 127);
            const float w00 = wx0 * wy0 * mx0 * my0;
            const float w01 = wx1 * wy0 * mx1 * my0;
            const float w10 = wx0 * wy1 * mx0 * my1;
            const float w11 = wx1 * wy1 * mx1 * my1;
            const float4 a = *(const float4*)(xb + (((cy0 << 7) + cx0) << 6) + 4 * lh);
            const float4 b = *(const float4*)(xb + (((cy0 << 7) + cx1) << 6) + 4 * lh);
            const float4 c = *(const float4*)(xb + (((cy1 << 7) + cx0) << 6) + 4 * lh);
            const float4 d = *(const float4*)(xb + (((cy1 << 7) + cx1) << 6) + 4 * lh);
            float v0 = w00 * a.x + w01 * b.x + w10 * c.x + w11 * d.x;
            float v1 = w00 * a.y + w01 * b.y + w10 * c.y + w11 * d.y;
            float v2 = w00 * a.z + w01 * b.z + w10 * c.z + w11 * d.z;
            float v3 = w00 * a.w + w01 * b.w + w10 * c.w + w11 * d.w;
            uint2 hi, lo;
            hi.x = pack_bf16x2(v0, v1);
            hi.y = pack_bf16x2(v2, v3);
            lo.x = pack_bf16x2(v0 - unpack_lo(hi.x), v1 - unpack_hi(hi.x));
            lo.y = pack_bf16x2(v2 - unpack_lo(hi.y), v3 - unpack_hi(hi.y));
            const int wix = AIDX(p, 2 * lh);
            *(uint2*)&A0[wix] = hi;
            *(uint2*)&A1[wix] = lo;
        }
    };

    // GEMM lane constants
    const int m0  = (wid & 3) * 32;
    const int n0  = (wid >> 2) * 32;
    const int n0g = wid >> 2;
    const int r   = lane >> 2;
    const int u   = lane & 3;
    const int l7   = lane & 7;
    const int swz  = l7 << 2;
    const int arow0 = m0 + l7 + (((lane >> 3) & 1) << 3);
    const int kbA   = ((lane >> 4) & 1) << 2;

    float acc[2][4][4];
#pragma unroll
    for (int mt = 0; mt < 2; mt++)
#pragma unroll
        for (int nt = 0; nt < 4; nt++)
#pragma unroll
            for (int q = 0; q < 4; q++) acc[mt][nt][q] = 0.f;

    // prologue: fill buffer 0 with kn=0
    sample_tile(0, 0);
    __syncthreads();

    for (int kn = 0; kn < KNPTS; kn++) {
        const int buf = kn & 1;
        const uint32_t a0b = sb + SM_AH + buf * 16384;
        const uint32_t a1b = sb + SM_AL + buf * 16384;
        const uint4* wf = g_wfrag + WIDX(kn, n0g, 0, 0, lane);

        // ---- GEMM(kn): A from smem (ldmatrix), B fragments straight from global ----
#pragma unroll
        for (int ks = 0; ks < 4; ks++) {
            uint32_t a0[2][4], a1[2][4];
#pragma unroll
            for (int mt = 0; mt < 2; mt++) {
                const int row = arow0 + mt * 16;
                const uint32_t off =
                    (uint32_t)(((row << 5) + ((ks * 8 + kbA) ^ swz)) << 2);
                ldm4(a0[mt], a0b + off);
                ldm4(a1[mt], a1b + off);
            }
#pragma unroll
            for (int nt = 0; nt < 4; nt++) {
                const uint4 q = __ldg(wf + (ks * 4 + nt) * 32);
#pragma unroll
                for (int mt = 0; mt < 2; mt++) {
                    MMA(acc[mt][nt], a1[mt], q.x, q.y);   // lo-x * hi-w
                    MMA(acc[mt][nt], a0[mt], q.z, q.w);   // hi-x * lo-w
                    MMA(acc[mt][nt], a0[mt], q.x, q.y);   // hi-x * hi-w
                }
            }
        }

        // ---- sample(kn+1) into the other buffer (overlaps MMA tail) ----
        if (kn + 1 < KNPTS) sample_tile(kn + 1, buf ^ 1);
        __syncthreads();
    }

    // ---- epilogue: stage C in smem (oc-major), then coalesced STG.128 ----
    float* Cs = (float*)smem;   // tiles dead after final sync
#pragma unroll
    for (int mt = 0; mt < 2; mt++)
#pragma unroll
        for (int nt = 0; nt < 4; nt++) {
            const int p  = m0 + mt * 16 + r;
            const int oc = n0 + nt * 8 + 2 * u;
            Cs[oc * CS_STRIDE + p]           = acc[mt][nt][0];
            Cs[(oc + 1) * CS_STRIDE + p]     = acc[mt][nt][1];
            Cs[oc * CS_STRIDE + p + 8]       = acc[mt][nt][2];
            Cs[(oc + 1) * CS_STRIDE + p + 8] = acc[mt][nt][3];
        }
    __syncthreads();
    float* ob = out + (((size_t)n * OC) << 14) + pixbase;
#pragma unroll
    for (int k = 0; k < 8; k++) {
        const int idx = tid + k * 256;
        const int oc = idx >> 5, fq = idx & 31;
        const float4 v = *(const float4*)(Cs + oc * CS_STRIDE + fq * 4);
        *(float4*)(ob + ((size_t)oc << 14) + fq * 4) = v;
    }
}

extern "C" void kernel_launch(void* const* d_in, const int* in_sizes, int n_in,
                              void* d_out, int out_size)
{
    const float* x      = (const float*)d_in[0];   // (4, 64, 128, 128)
    const float* offset = (const float*)d_in[1];   // (4, 18, 128, 128)
    const float* weight = (const float*)d_in[2];   // (64, 64, 9)
    float* out = (float*)d_out;                    // (4, 64, 128, 128)
    (void)in_sizes; (void)n_in; (void)out_size;

    static int smem_set = 0;
    if (!smem_set) {
        cudaFuncSetAttribute(dcn_mma_kernel,
                             cudaFuncAttributeMaxDynamicSharedMemorySize, SM_TOTAL);
        smem_set = 1;
    }
    nchw_to_nhwc_kernel<<<4 * 256, 256>>>(x);
    wsplit_kernel<<<(KNPTS * 2 * 4 * 4 * 32 + 255) / 256, 256>>>(weight);
    dcn_mma_kernel<<<NBLK, THREADS, SM_TOTAL>>>(offset, out);
}

// round 15
// speedup vs baseline: 1.1666x; 1.1666x over previous
#include <cuda_runtime.h>
#include <cstdint>

#define C_IN  64
#define OC    64
#define KNPTS 9
#define PLANE 16384
#define KTOT  576

#define THREADS 128
#define PIXB   64                   // pixels per block (M) = half an image row
#define NBLK   (4 * PLANE / PIXB)   // 1024

// ---- scratch (__device__ globals: allocation is forbidden) ----
__device__ float g_xhwc[(size_t)4 * PLANE * C_IN];   // NHWC x
// B in mma-fragment order: [kn][n0g][ks][nt][lane] -> {b0_hi, b1_hi, b0_lo, b1_lo}
__device__ uint4 g_wfrag[KNPTS * 2 * 4 * 4 * 32];
#define WIDX(kn, n0g, ks, nt, lane) \
    ((((((kn) * 2 + (n0g)) * 4 + (ks)) * 4 + (nt)) * 32) + (lane))
#define NWFRAG (KNPTS * 2 * 4 * 4 * 32)   // 9216

// ---- dynamic smem layout (bytes): double-buffered A tiles only ----
#define SM_AH     0                 // A hi [2] : 2 x 8192
#define SM_AL     16384             // A lo [2] : 2 x 8192
#define SM_TOTAL  32768
#define CS_STRIDE 68                // epilogue C stage row stride (floats)

// word-index swizzle (swizzle bits 2-4 only; 16B groups stay contiguous)
#define AIDX(p, kp)  (((p) << 5) + ((kp) ^ (((p) & 7) << 2)))

__device__ __forceinline__ uint32_t pack_bf16x2(float lo, float hi) {
    uint32_t r;   // d.hi = cvt(hi), d.lo = cvt(lo)
    asm("cvt.rn.bf16x2.f32 %0, %1, %2;" : "=r"(r) : "f"(hi), "f"(lo));
    return r;
}
__device__ __forceinline__ float unpack_lo(uint32_t w) { return __uint_as_float(w << 16); }
__device__ __forceinline__ float unpack_hi(uint32_t w) { return __uint_as_float(w & 0xFFFF0000u); }

__device__ __forceinline__ uint32_t smem_u32(const void* p) {
    uint32_t a;
    asm("{ .reg .u64 t; cvta.to.shared.u64 t, %1; cvt.u32.u64 %0, t; }" : "=r"(a) : "l"(p));
    return a;
}
__device__ __forceinline__ void ldm4(uint32_t* d, uint32_t addr) {
    asm volatile("ldmatrix.sync.aligned.m8n8.x4.shared.b16 {%0,%1,%2,%3}, [%4];"
                 : "=r"(d[0]), "=r"(d[1]), "=r"(d[2]), "=r"(d[3]) : "r"(addr));
}

#define MMA(C, A, B0r, B1r)                                                     \
    asm volatile("mma.sync.aligned.m16n8k16.row.col.f32.bf16.bf16.f32 "         \
                 "{%0,%1,%2,%3},{%4,%5,%6,%7},{%8,%9},{%0,%1,%2,%3};"           \
                 : "+f"(C[0]), "+f"(C[1]), "+f"(C[2]), "+f"(C[3])               \
                 : "r"(A[0]), "r"(A[1]), "r"(A[2]), "r"(A[3]), "r"(B0r), "r"(B1r))

// ------ fused prep: blocks <1024 transpose NCHW->NHWC; blocks >=1024 split weights ------
__global__ __launch_bounds__(256)
void prep_kernel(const float* __restrict__ x, const float* __restrict__ w)
{
    const int tid = threadIdx.x;
    if (blockIdx.x < 1024) {
        __shared__ float t[64][65];
        const int n   = blockIdx.x >> 8;
        const int hw0 = (blockIdx.x & 255) << 6;
        const float* xn = x + ((size_t)n << 20);
#pragma unroll
        for (int k = 0; k < 4; k++) {
            const int idx = tid + k * 256;
            const int c = idx >> 4, q = idx & 15;
            const float4 v = *(const float4*)(xn + ((size_t)c << 14) + hw0 + 4 * q);
            t[c][4 * q] = v.x; t[c][4 * q + 1] = v.y;
            t[c][4 * q + 2] = v.z; t[c][4 * q + 3] = v.w;
        }
        __syncthreads();
        float* dst = g_xhwc + (((size_t)n << 14) + hw0) * 64;
#pragma unroll
        for (int k = 0; k < 4; k++) {
            const int idx = tid + k * 256;
            const int p = idx >> 4, cq = idx & 15;
            float4 v;
            v.x = t[4 * cq][p]; v.y = t[4 * cq + 1][p];
            v.z = t[4 * cq + 2][p]; v.w = t[4 * cq + 3][p];
            *(float4*)(dst + (size_t)p * 64 + 4 * cq) = v;
        }
    } else {
        const int i = (blockIdx.x - 1024) * 256 + tid;   // fragment uint4 id
        if (i < NWFRAG) {
            const int lane = i & 31;
            const int nt   = (i >> 5) & 3;
            const int ks   = (i >> 7) & 3;
            const int n0g  = (i >> 9) & 1;
            const int kn   = i >> 10;
            const int oc   = n0g * 32 + nt * 8 + (lane >> 2);
            const int kp0  = ks * 8 + (lane & 3);
            uint4 q;
#pragma unroll
            for (int b = 0; b < 2; b++) {
                const int kp = kp0 + 4 * b;
                const float v0 = w[oc * KTOT + (2 * kp) * KNPTS + kn];
                const float v1 = w[oc * KTOT + (2 * kp + 1) * KNPTS + kn];
                const uint32_t hi = pack_bf16x2(v0, v1);
                const uint32_t lo = pack_bf16x2(v0 - unpack_lo(hi), v1 - unpack_hi(hi));
                if (b == 0) { q.x = hi; q.z = lo; }
                else        { q.y = hi; q.w = lo; }
            }
            g_wfrag[i] = q;
        }
    }
}

// ---- main kernel: 64-px blocks, double-buffered pipeline, 3xBF16 mma.sync ----
extern __shared__ char smem[];

__global__ __launch_bounds__(THREADS, 4)
void dcn_mma_kernel(const float* __restrict__ offset, float* __restrict__ out)
{
    const int tid  = threadIdx.x;
    const int wid  = tid >> 5;
    const int lane = tid & 31;
    const int n       = blockIdx.x >> 8;            // 256 blocks per image
    const int pixbase = (blockIdx.x & 255) << 6;    // 64 consecutive pixels
    const int ohc     = pixbase >> 7;               // constant oh for this block
    const int owc     = pixbase & 127;              // ow base (0 or 64)

    const float* offn = offset + (size_t)n * (KNPTS * 2) * PLANE + pixbase;
    const float* xb   = g_xhwc + (((size_t)n) << 14) * 64;
    const uint32_t sb = smem_u32(smem);

    const int tg = tid >> 4;        // sampling task group 0..7
    const int lh = tid & 15;        // channel quad owner: channels 4lh..4lh+3

    // sampling of one (kn, buf) tile: 64 pixels x 64 ch -> bf16 hi/lo into A
    auto sample_tile = [&](int kn, int buf) {
        uint32_t* A0 = (uint32_t*)(smem + SM_AH + buf * 8192);
        uint32_t* A1 = (uint32_t*)(smem + SM_AL + buf * 8192);
        const float* offy_p = offn + (2 * kn) * PLANE;
        const float* offx_p = offn + (2 * kn + 1) * PLANE;
#pragma unroll
        for (int it = 0; it < 8; it++) {
            const int p = it * 8 + tg;                  // local pixel 0..63
            const float iy = (float)ohc + offy_p[p];
            const float ix = (float)(owc + p) + offx_p[p];
            const float y0f = floorf(iy), x0f = floorf(ix);
            const float wy1 = iy - y0f,  wx1 = ix - x0f;
            const float wy0 = 1.f - wy1, wx0 = 1.f - wx1;
            const int x0 = (int)x0f, y0 = (int)y0f;
            const int x1 = x0 + 1,  y1 = y0 + 1;
            const float mx0 = ((unsigned)x0 < 128u) ? 1.f : 0.f;
            const float mx1 = ((unsigned)x1 < 128u) ? 1.f : 0.f;
            const float my0 = ((unsigned)y0 < 128u) ? 1.f : 0.f;
            const float my1 = ((unsigned)y1 < 128u) ? 1.f : 0.f;
            const int cx0 = min(max(x0, 0), 127), cx1 = min(max(x1, 0), 127);
            const int cy0 = min(max(y0, 0), 127), cy1 = min(max(y1, 0), 127);
            const float w00 = wx0 * wy0 * mx0 * my0;
            const float w01 = wx1 * wy0 * mx1 * my0;
            const float w10 = wx0 * wy1 * mx0 * my1;
            const float w11 = wx1 * wy1 * mx1 * my1;
            const float4 a = *(const float4*)(xb + (((cy0 << 7) + cx0) << 6) + 4 * lh);
            const float4 b = *(const float4*)(xb + (((cy0 << 7) + cx1) << 6) + 4 * lh);
            const float4 c = *(const float4*)(xb + (((cy1 << 7) + cx0) << 6) + 4 * lh);
            const float4 d = *(const float4*)(xb + (((cy1 << 7) + cx1) << 6) + 4 * lh);
            float v0 = w00 * a.x + w01 * b.x + w10 * c.x + w11 * d.x;
            float v1 = w00 * a.y + w01 * b.y + w10 * c.y + w11 * d.y;
            float v2 = w00 * a.z + w01 * b.z + w10 * c.z + w11 * d.z;
            float v3 = w00 * a.w + w01 * b.w + w10 * c.w + w11 * d.w;
            uint2 hi, lo;
            hi.x = pack_bf16x2(v0, v1);
            hi.y = pack_bf16x2(v2, v3);
            lo.x = pack_bf16x2(v0 - unpack_lo(hi.x), v1 - unpack_hi(hi.x));
            lo.y = pack_bf16x2(v2 - unpack_lo(hi.y), v3 - unpack_hi(hi.y));
            const int wix = AIDX(p, 2 * lh);
            *(uint2*)&A0[wix] = hi;
            *(uint2*)&A1[wix] = lo;
        }
    };

    // GEMM lane constants: 2 warps along M, 2 along N; warp tile 32x32
    const int m0  = (wid & 1) * 32;
    const int n0  = (wid >> 1) * 32;
    const int n0g = wid >> 1;
    const int r   = lane >> 2;
    const int u   = lane & 3;
    const int l7   = lane & 7;
    const int swz  = l7 << 2;
    const int arow0 = m0 + l7 + (((lane >> 3) & 1) << 3);
    const int kbA   = ((lane >> 4) & 1) << 2;

    float acc[2][4][4];
#pragma unroll
    for (int mt = 0; mt < 2; mt++)
#pragma unroll
        for (int nt = 0; nt < 4; nt++)
#pragma unroll
            for (int q = 0; q < 4; q++) acc[mt][nt][q] = 0.f;

    // prologue: fill buffer 0 with kn=0
    sample_tile(0, 0);
    __syncthreads();

    for (int kn = 0; kn < KNPTS; kn++) {
        const int buf = kn & 1;
        const uint32_t a0b = sb + SM_AH + buf * 8192;
        const uint32_t a1b = sb + SM_AL + buf * 8192;
        const uint4* wf = g_wfrag + WIDX(kn, n0g, 0, 0, lane);

        // ---- GEMM(kn): A from smem (ldmatrix), B fragments straight from global ----
#pragma unroll
        for (int ks = 0; ks < 4; ks++) {
            uint32_t a0[2][4], a1[2][4];
#pragma unroll
            for (int mt = 0; mt < 2; mt++) {
                const int row = arow0 + mt * 16;
                const uint32_t off =
                    (uint32_t)(((row << 5) + ((ks * 8 + kbA) ^ swz)) << 2);
                ldm4(a0[mt], a0b + off);
                ldm4(a1[mt], a1b + off);
            }
#pragma unroll
            for (int nt = 0; nt < 4; nt++) {
                const uint4 q = __ldg(wf + (ks * 4 + nt) * 32);
#pragma unroll
                for (int mt = 0; mt < 2; mt++) {
                    MMA(acc[mt][nt], a1[mt], q.x, q.y);   // lo-x * hi-w
                    MMA(acc[mt][nt], a0[mt], q.z, q.w);   // hi-x * lo-w
                    MMA(acc[mt][nt], a0[mt], q.x, q.y);   // hi-x * hi-w
                }
            }
        }

        // ---- sample(kn+1) into the other buffer (overlaps MMA tail) ----
        if (kn + 1 < KNPTS) sample_tile(kn + 1, buf ^ 1);
        __syncthreads();
    }

    // ---- epilogue: stage C in smem (oc-major), then coalesced STG.128 ----
    float* Cs = (float*)smem;   // 64 x CS_STRIDE floats = 17408 B (tiles dead)
#pragma unroll
    for (int mt = 0; mt < 2; mt++)
#pragma unroll
        for (int nt = 0; nt < 4; nt++) {
            const int p  = m0 + mt * 16 + r;
            const int oc = n0 + nt * 8 + 2 * u;
            Cs[oc * CS_STRIDE + p]           = acc[mt][nt][0];
            Cs[(oc + 1) * CS_STRIDE + p]     = acc[mt][nt][1];
            Cs[oc * CS_STRIDE + p + 8]       = acc[mt][nt][2];
            Cs[(oc + 1) * CS_STRIDE + p + 8] = acc[mt][nt][3];
        }
    __syncthreads();
    float* ob = out + (((size_t)n * OC) << 14) + pixbase;
#pragma unroll
    for (int k = 0; k < 8; k++) {
        const int idx = tid + k * 128;          // 1024 float4s: 64 oc x 16
        const int oc = idx >> 4, fq = idx & 15;
        const float4 v = *(const float4*)(Cs + oc * CS_STRIDE + fq * 4);
        *(float4*)(ob + ((size_t)oc << 14) + fq * 4) = v;
    }
}

extern "C" void kernel_launch(void* const* d_in, const int* in_sizes, int n_in,
                              void* d_out, int out_size)
{
    const float* x      = (const float*)d_in[0];   // (4, 64, 128, 128)
    const float* offset = (const float*)d_in[1];   // (4, 18, 128, 128)
    const float* weight = (const float*)d_in[2];   // (64, 64, 9)
    float* out = (float*)d_out;                    // (4, 64, 128, 128)
    (void)in_sizes; (void)n_in; (void)out_size;

    static int smem_set = 0;
    if (!smem_set) {
        cudaFuncSetAttribute(dcn_mma_kernel,
                             cudaFuncAttributeMaxDynamicSharedMemorySize, SM_TOTAL);
        smem_set = 1;
    }
    prep_kernel<<<1024 + (NWFRAG + 255) / 256, 256>>>(x, weight);
    dcn_mma_kernel<<<NBLK, THREADS, SM_TOTAL>>>(offset, out);
}